// round 9
// baseline (speedup 1.0000x reference)
#include <cuda_runtime.h>

#define N_NODES 10000
#define N_EDGES 160000
#define D1 128
#define D2 256
#define D3 512

#define GRID 148
#define TPB  1024
#define GT   (GRID * TPB)        // 151552
#define ROWSTRIDE (GT / 128)     // 1184 rows per sweep in phase P4

// ---- persistent scratch (zero at load; re-zeroed at tail of every run) ----
// pair1[n] = (g1[n], s[n]) ; pair2[n] = (a2[n], t[n])
__device__ __align__(16) float2 g_p1[N_NODES];
__device__ __align__(16) float2 g_p2[N_NODES];
__device__ float g_a3[N_NODES];
__device__ float g_W12[D2];     // W1 @ W2   (plain stores)
__device__ float g_bW2[D2];     // b1 @ W2
// collapsed, PRE-HALVED weight vectors: [P/2 | Q/2 | R/2 | b3/2] (plain stores)
__device__ __align__(16) float g_PQRB[4 * D3];

// ---- grid barrier (count==0 between barriers; gen monotonic) ----
__device__ int g_bar_count;
__device__ volatile int g_bar_gen;

__device__ __forceinline__ void grid_bar() {
    __threadfence();
    __syncthreads();
    if (threadIdx.x == 0) {
        int gen = g_bar_gen;                 // snapshot BEFORE arriving
        if (atomicAdd(&g_bar_count, 1) == GRID - 1) {
            g_bar_count = 0;
            __threadfence();
            g_bar_gen = gen + 1;
        } else {
            while (g_bar_gen == gen) { }     // tight spin (~L2 RTT wakeup)
        }
    }
    __syncthreads();
}

__device__ __forceinline__ void red_add_v2(float2* addr, float a, float b) {
    asm volatile("red.global.add.v2.f32 [%0], {%1, %2};"
                 :: "l"(addr), "f"(a), "f"(b) : "memory");
}

__device__ __forceinline__ float fast_tanh(float h) {
    float r;
    asm("tanh.approx.f32 %0, %1;" : "=f"(r) : "f"(h));
    return r;
}

__global__ void __launch_bounds__(TPB, 1)
fused_gcn_kernel(const float* __restrict__ x,
                 const int*   __restrict__ ei,
                 const float* __restrict__ ew,
                 const float* __restrict__ W1,
                 const float* __restrict__ b1,
                 const float* __restrict__ W2,
                 const float* __restrict__ b2,
                 const float* __restrict__ W3,
                 const float* __restrict__ b3,
                 float* __restrict__ out) {
    __shared__ float s_red[1024];

    const int tid  = threadIdx.x;
    const int bid  = blockIdx.x;
    const int gtid = bid * TPB + tid;

    // ===== P1: edge1 (blocks 0-143) || W12/bW2 GEMV (144-145) || b3/2 (146) =
    if (bid < 144) {
        // (g1,s)[dst] += (w*x[src], w)
        for (int e = bid * TPB + tid; e < N_EDGES; e += 144 * TPB) {
            int src = ei[e];
            int dst = ei[N_EDGES + e];
            float w = ew[e];
            red_add_v2(&g_p1[dst], w * x[src], w);
        }
    } else if (bid < 146) {
        // one block per target vector: 256 cols x 4 j-chunks of 32
        const float* a = (bid == 144) ? W1 : b1;
        int k  = tid & 255;
        int jc = tid >> 8;              // 0..3
        int j0 = jc * 32;
        float acc = 0.f;
        #pragma unroll 8
        for (int jj = 0; jj < 32; jj++) {
            int j = j0 + jj;
            acc += a[j] * W2[j * D2 + k];
        }
        s_red[jc * 256 + k] = acc;
        __syncthreads();
        if (tid < 256) {
            float v = s_red[tid] + s_red[256 + tid] + s_red[512 + tid] + s_red[768 + tid];
            if (bid == 144) g_W12[tid] = v;
            else            g_bW2[tid] = v;
        }
    } else if (bid == 146) {
        if (tid < D3) g_PQRB[3 * D3 + tid] = 0.5f * b3[tid];
    }

    grid_bar();

    // ===== P2: edge2 (blocks 0-135) || P/Q/R GEMV (blocks 136-147) ==========
    if (bid < 136) {
        // (a2,t)[dst] += w*(g1,s)[src]
        for (int e = bid * TPB + tid; e < N_EDGES; e += 136 * TPB) {
            int src = ei[e];
            int dst = ei[N_EDGES + e];
            float w = ew[e];
            float2 p = g_p1[src];
            red_add_v2(&g_p2[dst], w * p.x, w * p.y);
        }
    } else {
        // 12 blocks: vec in {P,Q,R} x 4 col-quarters; 8 k-chunks of 32/thread
        int unit = bid - 136;           // 0..11
        int vec  = unit >> 2;           // 0..2
        int q    = unit & 3;
        int col  = q * 128 + (tid & 127);
        int c    = tid >> 7;            // 0..7
        const float* coef = (vec == 0) ? g_W12 : ((vec == 1) ? g_bW2 : b2);
        int j0 = c * 32;
        float acc = 0.f;
        #pragma unroll 8
        for (int jj = 0; jj < 32; jj++) {
            int j = j0 + jj;
            acc += coef[j] * W3[j * D3 + col];
        }
        s_red[c * 128 + (tid & 127)] = acc;
        __syncthreads();
        if (tid < 128) {
            float v = 0.f;
            #pragma unroll
            for (int c2 = 0; c2 < 8; c2++) v += s_red[c2 * 128 + tid];
            g_PQRB[vec * D3 + q * 128 + tid] = 0.5f * v;
        }
    }

    grid_bar();

    // ===== P3: edge3 (all blocks): a3[dst] += w * a2[src] ===================
    for (int e = gtid; e < N_EDGES; e += GT) {
        int src = ei[e];
        int dst = ei[N_EDGES + e];
        float w = ew[e];
        atomicAdd(&g_a3[dst], w * g_p2[src].x);
    }

    grid_bar();

    // ===== P4: out = 0.5*tanh(a3*P' + t*Q' + s*R' + B') + 0.5; then re-zero =
    {
        int j4 = (gtid & 127) << 2;     // loop-invariant feature offset
        float4 P = *reinterpret_cast<const float4*>(&g_PQRB[j4]);
        float4 Q = *reinterpret_cast<const float4*>(&g_PQRB[D3 + j4]);
        float4 R = *reinterpret_cast<const float4*>(&g_PQRB[2 * D3 + j4]);
        float4 B = *reinterpret_cast<const float4*>(&g_PQRB[3 * D3 + j4]);

        for (int n = gtid >> 7; n < N_NODES; n += ROWSTRIDE) {
            float a3 = g_a3[n];
            float2 p2 = g_p2[n];   // (a2, t)
            float2 p1 = g_p1[n];   // (g1, s)
            float tt = p2.y;
            float ss = p1.y;

            float4 v;  // = logit/2 (weights pre-halved)
            v.x = fmaf(a3, P.x, fmaf(tt, Q.x, fmaf(ss, R.x, B.x)));
            v.y = fmaf(a3, P.y, fmaf(tt, Q.y, fmaf(ss, R.y, B.y)));
            v.z = fmaf(a3, P.z, fmaf(tt, Q.z, fmaf(ss, R.z, B.z)));
            v.w = fmaf(a3, P.w, fmaf(tt, Q.w, fmaf(ss, R.w, B.w)));

            v.x = fmaf(0.5f, fast_tanh(v.x), 0.5f);
            v.y = fmaf(0.5f, fast_tanh(v.y), 0.5f);
            v.z = fmaf(0.5f, fast_tanh(v.z), 0.5f);
            v.w = fmaf(0.5f, fast_tanh(v.w), 0.5f);

            *reinterpret_cast<float4*>(&out[n * D3 + j4]) = v;
        }

        // Tail re-zero: each block zeroes exactly the rows it just read.
        // Row n's 128 readers are 128 contiguous gtids, all inside this block
        // (128 | 1024), so __syncthreads() orders reads before zeroing.
        __syncthreads();
        for (int n = gtid >> 7; n < N_NODES; n += ROWSTRIDE) {
            if ((tid & 127) == 0) {
                g_p1[n] = make_float2(0.f, 0.f);
                g_p2[n] = make_float2(0.f, 0.f);
                g_a3[n] = 0.f;
            }
        }
    }
}

extern "C" void kernel_launch(void* const* d_in, const int* in_sizes, int n_in,
                              void* d_out, int out_size) {
    const float* x  = (const float*)d_in[0];
    const int*   ei = (const int*)d_in[1];
    const float* ew = (const float*)d_in[2];
    const float* W1 = (const float*)d_in[3];
    const float* b1 = (const float*)d_in[4];
    const float* W2 = (const float*)d_in[5];
    const float* b2 = (const float*)d_in[6];
    const float* W3 = (const float*)d_in[7];
    const float* b3 = (const float*)d_in[8];
    float* out = (float*)d_out;

    fused_gcn_kernel<<<GRID, TPB>>>(x, ei, ew, W1, b1, W2, b2, W3, b3, out);
}

// round 11
// speedup vs baseline: 1.1919x; 1.1919x over previous
#include <cuda_runtime.h>

#define N_NODES 10000
#define N_EDGES 160000
#define D1 128
#define D2 256
#define D3 512

#define GRID 148
#define TPB  1024
#define GT   (GRID * TPB)        // 151552
#define ROWSTRIDE (GT / 128)     // 1184 rows per sweep in phase P4

// ---- persistent scratch (zero at load; re-zeroed at tail of every run) ----
// pair1[n] = (g1[n], s[n]) ; pair2[n] = (a2[n], t[n])
__device__ __align__(16) float2 g_p1[N_NODES];
__device__ __align__(16) float2 g_p2[N_NODES];
__device__ float g_a3[N_NODES];
__device__ float g_W12[D2];     // W1 @ W2   (plain stores each run)
__device__ float g_bW2[D2];     // b1 @ W2
// collapsed, PRE-HALVED weight vectors: [P/2 | Q/2 | R/2 | b3/2] (plain stores)
__device__ __align__(16) float g_PQRB[4 * D3];

// ---- grid barrier (count==0 between barriers; gen monotonic) ----
__device__ int g_bar_count;
__device__ volatile int g_bar_gen;

__device__ __forceinline__ void grid_bar() {
    __threadfence();
    __syncthreads();
    if (threadIdx.x == 0) {
        int gen = g_bar_gen;                 // snapshot BEFORE arriving
        if (atomicAdd(&g_bar_count, 1) == GRID - 1) {
            g_bar_count = 0;
            __threadfence();
            g_bar_gen = gen + 1;
        } else {
            while (g_bar_gen == gen) { __nanosleep(40); }
        }
    }
    __syncthreads();
}

__device__ __forceinline__ void red_add_v2(float2* addr, float a, float b) {
    asm volatile("red.global.add.v2.f32 [%0], {%1, %2};"
                 :: "l"(addr), "f"(a), "f"(b) : "memory");
}

__device__ __forceinline__ float fast_tanh(float h) {
    float r;
    asm("tanh.approx.f32 %0, %1;" : "=f"(r) : "f"(h));
    return r;
}

// ---- packed f32x2 helpers (ptxas emits FFMA2 only via PTX fma.rn.f32x2) ----
__device__ __forceinline__ unsigned long long pk2(float lo, float hi) {
    unsigned long long r;
    asm("mov.b64 %0, {%1, %2};" : "=l"(r) : "f"(lo), "f"(hi));
    return r;
}
__device__ __forceinline__ void upk2(float& lo, float& hi, unsigned long long v) {
    asm("mov.b64 {%0, %1}, %2;" : "=f"(lo), "=f"(hi) : "l"(v));
}
__device__ __forceinline__ unsigned long long fma2(unsigned long long a,
                                                   unsigned long long b,
                                                   unsigned long long c) {
    unsigned long long d;
    asm("fma.rn.f32x2 %0, %1, %2, %3;" : "=l"(d) : "l"(a), "l"(b), "l"(c));
    return d;
}

__global__ void __launch_bounds__(TPB, 1)
fused_gcn_kernel(const float* __restrict__ x,
                 const int*   __restrict__ ei,
                 const float* __restrict__ ew,
                 const float* __restrict__ W1,
                 const float* __restrict__ b1,
                 const float* __restrict__ W2,
                 const float* __restrict__ b2,
                 const float* __restrict__ W3,
                 const float* __restrict__ b3,
                 float* __restrict__ out) {
    __shared__ float s_red[1024];

    const int tid  = threadIdx.x;
    const int bid  = blockIdx.x;
    const int gtid = bid * TPB + tid;

    // ---- cache this thread's edges for ALL three passes ----
    const bool has1 = (gtid + GT) < N_EDGES;        // gtid < 8448
    int src0 = ei[gtid];
    int dst0 = ei[N_EDGES + gtid];
    float w0 = ew[gtid];
    int src1 = 0, dst1 = 0; float w1 = 0.f;
    if (has1) {
        src1 = ei[gtid + GT];
        dst1 = ei[N_EDGES + gtid + GT];
        w1   = ew[gtid + GT];
    }

    // ===== P1: edge1 (all) || W12/bW2 GEMV (blocks 144-145) || b3/2 (146) ===
    // (g1,s)[dst] += (w*x[src], w)
    red_add_v2(&g_p1[dst0], w0 * x[src0], w0);
    if (has1) red_add_v2(&g_p1[dst1], w1 * x[src1], w1);

    if (bid == 144 || bid == 145) {
        // one block per target vector: 256 cols x 4 j-chunks of 32
        const float* a = (bid == 144) ? W1 : b1;
        int k  = tid & 255;
        int jc = tid >> 8;              // 0..3
        int j0 = jc * 32;
        float acc = 0.f;
        #pragma unroll 8
        for (int jj = 0; jj < 32; jj++) {
            int j = j0 + jj;
            acc += a[j] * W2[j * D2 + k];
        }
        s_red[jc * 256 + k] = acc;
        __syncthreads();
        if (tid < 256) {
            float v = s_red[tid] + s_red[256 + tid] + s_red[512 + tid] + s_red[768 + tid];
            if (bid == 144) g_W12[tid] = v;
            else            g_bW2[tid] = v;
        }
    } else if (bid == 146) {
        if (tid < D3) g_PQRB[3 * D3 + tid] = 0.5f * b3[tid];
    }

    grid_bar();

    // ===== P2: edge2 (all) || P/Q/R GEMV (blocks 136-147) ===================
    // (a2,t)[dst] += w*(g1,s)[src]
    {
        float2 p = g_p1[src0];
        red_add_v2(&g_p2[dst0], w0 * p.x, w0 * p.y);
        if (has1) {
            float2 q = g_p1[src1];
            red_add_v2(&g_p2[dst1], w1 * q.x, w1 * q.y);
        }
    }

    if (bid >= 136) {
        // 12 blocks: vec in {P,Q,R} x 4 col-quarters; 8 k-chunks of 32/thread
        int unit = bid - 136;           // 0..11
        int vec  = unit >> 2;           // 0..2
        int q    = unit & 3;
        int col  = q * 128 + (tid & 127);
        int c    = tid >> 7;            // 0..7
        const float* coef = (vec == 0) ? g_W12 : ((vec == 1) ? g_bW2 : b2);
        int j0 = c * 32;
        float acc = 0.f;
        #pragma unroll 8
        for (int jj = 0; jj < 32; jj++) {
            int j = j0 + jj;
            acc += coef[j] * W3[j * D3 + col];
        }
        s_red[c * 128 + (tid & 127)] = acc;
        __syncthreads();
        if (tid < 128) {
            float v = 0.f;
            #pragma unroll
            for (int c2 = 0; c2 < 8; c2++) v += s_red[c2 * 128 + tid];
            g_PQRB[vec * D3 + q * 128 + tid] = 0.5f * v;
        }
    }

    grid_bar();

    // ===== P3: edge3 (all): a3[dst] += w * a2[src] ==========================
    atomicAdd(&g_a3[dst0], w0 * g_p2[src0].x);
    if (has1) atomicAdd(&g_a3[dst1], w1 * g_p2[src1].x);

    grid_bar();

    // ===== P4: out = 0.5*tanh(a3*P' + t*Q' + s*R' + B') + 0.5; then re-zero =
    {
        int j4 = (gtid & 127) << 2;     // loop-invariant feature offset
        float4 P = *reinterpret_cast<const float4*>(&g_PQRB[j4]);
        float4 Q = *reinterpret_cast<const float4*>(&g_PQRB[D3 + j4]);
        float4 R = *reinterpret_cast<const float4*>(&g_PQRB[2 * D3 + j4]);
        float4 B = *reinterpret_cast<const float4*>(&g_PQRB[3 * D3 + j4]);

        unsigned long long P01 = pk2(P.x, P.y), P23 = pk2(P.z, P.w);
        unsigned long long Q01 = pk2(Q.x, Q.y), Q23 = pk2(Q.z, Q.w);
        unsigned long long R01 = pk2(R.x, R.y), R23 = pk2(R.z, R.w);
        unsigned long long B01 = pk2(B.x, B.y), B23 = pk2(B.z, B.w);

        for (int n = gtid >> 7; n < N_NODES; n += ROWSTRIDE) {
            float a3 = g_a3[n];
            float tt = g_p2[n].y;
            float ss = g_p1[n].y;

            unsigned long long A2v = pk2(a3, a3);
            unsigned long long T2  = pk2(tt, tt);
            unsigned long long S2  = pk2(ss, ss);

            unsigned long long u01 = fma2(A2v, P01, fma2(T2, Q01, fma2(S2, R01, B01)));
            unsigned long long u23 = fma2(A2v, P23, fma2(T2, Q23, fma2(S2, R23, B23)));

            float4 v;
            upk2(v.x, v.y, u01);
            upk2(v.z, v.w, u23);

            v.x = fmaf(0.5f, fast_tanh(v.x), 0.5f);
            v.y = fmaf(0.5f, fast_tanh(v.y), 0.5f);
            v.z = fmaf(0.5f, fast_tanh(v.z), 0.5f);
            v.w = fmaf(0.5f, fast_tanh(v.w), 0.5f);

            *reinterpret_cast<float4*>(&out[n * D3 + j4]) = v;
        }

        // Tail re-zero: each block zeroes exactly the rows it just read.
        // Row n's 128 readers are 128 contiguous gtids, all inside this block
        // (128 | 1024), so __syncthreads() orders reads before zeroing.
        __syncthreads();
        for (int n = gtid >> 7; n < N_NODES; n += ROWSTRIDE) {
            if ((tid & 127) == 0) {
                g_p1[n] = make_float2(0.f, 0.f);
                g_p2[n] = make_float2(0.f, 0.f);
                g_a3[n] = 0.f;
            }
        }
    }
}

extern "C" void kernel_launch(void* const* d_in, const int* in_sizes, int n_in,
                              void* d_out, int out_size) {
    const float* x  = (const float*)d_in[0];
    const int*   ei = (const int*)d_in[1];
    const float* ew = (const float*)d_in[2];
    const float* W1 = (const float*)d_in[3];
    const float* b1 = (const float*)d_in[4];
    const float* W2 = (const float*)d_in[5];
    const float* b2 = (const float*)d_in[6];
    const float* W3 = (const float*)d_in[7];
    const float* b3 = (const float*)d_in[8];
    float* out = (float*)d_out;

    fused_gcn_kernel<<<GRID, TPB>>>(x, ei, ew, W1, b1, W2, b2, W3, b3, out);
}